// round 15
// baseline (speedup 1.0000x reference)
#include <cuda_runtime.h>
#include <cuda_fp16.h>
#include <math.h>
#include <stdint.h>

#define ZD      8
#define HID     128
#define NPIX    65536
#define TILE_R  256          // 16 warps x 16 rows
#define NTHREADS 512
#define GRID_P  148

// ---------------- SMEM byte offsets ----------------------------------------
#define OFF_W0   0            // 128x128 half [n][k] swizzled = 32768
#define OFF_W1   32768
#define OFF_W2   65536
#define OFF_WO16 98304        // 16 rows x 128 half (wout^T padded) = 4096
#define OFF_ZB   102400       // 16 images x 128 f32 (b0 + z@w0[0:8]) = 8192
#define OFF_B1   110592       // 128 f32 = 512
#define OFF_B2   111104       // 128 f32 = 512
#define SMEM_BYTES 111616

// half-index swizzle for weights: element (n,k) of [n][128]; 16B granules
#define HSW(n, k) ((n) * 128 + (((((k) >> 3) ^ ((n) & 7)) << 3) | ((k) & 7)))

__device__ __forceinline__ uint32_t smem_u32(const void* p) {
    uint32_t a;
    asm("{ .reg .u64 t; cvta.to.shared.u64 t, %1; cvt.u32.u64 %0, t; }" : "=r"(a) : "l"(p));
    return a;
}
__device__ __forceinline__ void ldsm4(uint32_t& r0, uint32_t& r1, uint32_t& r2, uint32_t& r3,
                                      uint32_t addr) {
    asm volatile("ldmatrix.sync.aligned.m8n8.x4.shared.b16 {%0,%1,%2,%3}, [%4];"
                 : "=r"(r0), "=r"(r1), "=r"(r2), "=r"(r3) : "r"(addr));
}
__device__ __forceinline__ void mma_f16(float c[4],
                                        uint32_t a0, uint32_t a1, uint32_t a2, uint32_t a3,
                                        uint32_t b0, uint32_t b1) {
    asm volatile("mma.sync.aligned.m16n8k16.row.col.f32.f16.f16.f32 "
                 "{%0,%1,%2,%3}, {%4,%5,%6,%7}, {%8,%9}, {%0,%1,%2,%3};"
                 : "+f"(c[0]), "+f"(c[1]), "+f"(c[2]), "+f"(c[3])
                 : "r"(a0), "r"(a1), "r"(a2), "r"(a3), "r"(b0), "r"(b1));
}
__device__ __forceinline__ uint32_t packh2(float a, float b) {
    __half2 h = __floats2half2_rn(a, b);
    return *reinterpret_cast<uint32_t*>(&h);
}
// pack two f32 (bias already inside acc) + relu, packed half2
__device__ __forceinline__ uint32_t h2_relu_pack(float a, float b) {
    __half2 v = __floats2half2_rn(a, b);
    __half2 zz = __float2half2_rn(0.f);
    v = __hmax2(v, zz);
    return *reinterpret_cast<uint32_t*>(&v);
}
__device__ __forceinline__ void fast_sincos(float x, float* s, float* c) {
    *s = __sinf(x);
    *c = __cosf(x);
}

// one full layer: acc[16][4] = bias + A(aF) @ W(128x128); bias f32 init.
__device__ __forceinline__ void layer_mma(const uint32_t aF[8][4], float acc[16][4],
                                          uint32_t wB0, uint32_t bSelKg, uint32_t nl7,
                                          const float* __restrict__ biasRow, int q) {
    #pragma unroll
    for (int nt = 0; nt < 16; ++nt) {
        float2 bb = *reinterpret_cast<const float2*>(biasRow + 8 * nt + 2 * q);
        acc[nt][0] = bb.x; acc[nt][1] = bb.y;
        acc[nt][2] = bb.x; acc[nt][3] = bb.y;
    }

    #pragma unroll
    for (int kt = 0; kt < 8; ++kt) {
        // swizzle XOR is independent of ng (n & 7 == nLoc & 7)
        uint32_t base = wB0 + ((((uint32_t)(2 * kt) + bSelKg) ^ nl7) << 4);
        #pragma unroll
        for (int hg = 0; hg < 2; ++hg) {
            uint32_t bf[8][2];
            #pragma unroll
            for (int ngl = 0; ngl < 4; ++ngl) {
                uint32_t ad = base + (uint32_t)(hg * 4 + ngl) * 4096;
                ldsm4(bf[2 * ngl][0], bf[2 * ngl][1],
                      bf[2 * ngl + 1][0], bf[2 * ngl + 1][1], ad);
            }
            #pragma unroll
            for (int ntl = 0; ntl < 8; ++ntl)
                mma_f16(acc[hg * 8 + ntl], aF[kt][0], aF[kt][1], aF[kt][2], aF[kt][3],
                        bf[ntl][0], bf[ntl][1]);
        }
    }
}

// epilogue: relu + pack -> next layer's A fragments (bias already in acc)
__device__ __forceinline__ void epi_pack(uint32_t aF[8][4], const float acc[16][4]) {
    #pragma unroll
    for (int kt = 0; kt < 8; ++kt) {
        aF[kt][0] = h2_relu_pack(acc[2 * kt][0],     acc[2 * kt][1]);
        aF[kt][1] = h2_relu_pack(acc[2 * kt][2],     acc[2 * kt][3]);
        aF[kt][2] = h2_relu_pack(acc[2 * kt + 1][0], acc[2 * kt + 1][1]);
        aF[kt][3] = h2_relu_pack(acc[2 * kt + 1][2], acc[2 * kt + 1][3]);
    }
}

__global__ void ifv_zero_kernel(float4* __restrict__ out, int n4) {
    int i = blockIdx.x * blockDim.x + threadIdx.x;
    int stride = gridDim.x * blockDim.x;
    float4 zv = make_float4(0.f, 0.f, 0.f, 0.f);
    for (; i < n4; i += stride) out[i] = zv;
}

__global__ __launch_bounds__(NTHREADS)
void ifv_binit_kernel(const float* __restrict__ z,
                      const float* __restrict__ rotmat,
                      const float* __restrict__ pc,
                      const int*   __restrict__ midx,
                      const float* __restrict__ bg,
                      const float* __restrict__ w0, const float* __restrict__ b0,
                      const float* __restrict__ w1, const float* __restrict__ b1,
                      const float* __restrict__ w2, const float* __restrict__ b2,
                      const float* __restrict__ wout, const float* __restrict__ bout,
                      float* __restrict__ out, int M, int tiles, int total, int nimg)
{
    extern __shared__ char smem[];
    __half*    sW0  = (__half*)(smem + OFF_W0);
    __half*    sW1  = (__half*)(smem + OFF_W1);
    __half*    sW2  = (__half*)(smem + OFF_W2);
    __half*    sWo  = (__half*)(smem + OFF_WO16);    // 16x128, rows 2..15 zero
    float*     sZB  = (float*)(smem + OFF_ZB);       // per image: 128 f32
    float*     sB1  = (float*)(smem + OFF_B1);
    float*     sB2  = (float*)(smem + OFF_B2);

    const uint32_t sbase = smem_u32(smem);
    const int t    = threadIdx.x;
    const int wid  = t >> 5;
    const int lane = t & 31;
    const int q    = lane & 3;
    const int rsub = lane >> 2;                  // 0..7

    // ---------------- one-time staging (weights fp16 [n][k] swizzled) ------
    for (int i = t; i < HID * HID; i += NTHREADS) {
        int k = i >> 7, n = i & 127;
        int sw = HSW(n, k);
        sW0[sw] = __float2half(w0[(k + ZD) * HID + n]);  // z rows folded into zb
        sW1[sw] = __float2half(w1[k * HID + n]);
        sW2[sw] = __float2half(w2[k * HID + n]);
    }
    // wout^T panel: row n (0..15), col k; rows 0,1 = wout[:,0], wout[:,1]
    for (int i = t; i < 16 * HID; i += NTHREADS) {
        int n = i >> 7, k = i & 127;
        float v = (n < 2) ? wout[k * 2 + n] : 0.f;
        sWo[HSW(n, k)] = __float2half(v);
    }
    // zb[b][c] = b0[c] + z[b] . w0[0:8][c]  (f32, feeds layer-0 acc init)
    for (int i = t; i < nimg * HID; i += NTHREADS) {
        int bb = i >> 7, c = i & 127;
        float a = b0[c];
        #pragma unroll
        for (int k = 0; k < ZD; ++k)
            a = fmaf(z[bb * ZD + k], w0[k * HID + c], a);
        sZB[i] = a;
    }
    if (t < HID) {
        sB1[t] = b1[t];
        sB2[t] = b2[t];
    }
    __syncthreads();   // the ONLY block barrier

    const uint32_t bSelKg = (uint32_t)((lane >> 3) & 1);
    const uint32_t nLoc   = (uint32_t)(((lane >> 4) << 3) + (lane & 7));
    const uint32_t nl7    = nLoc & 7;
    const float bo0 = bout[0], bo1 = bout[1];
    const float TWOPI = 6.28318530717958647692f;

    int unit = blockIdx.x;
    while (unit < total) {
        const int b  = unit / tiles;
        const int m0 = (unit - b * tiles) * TILE_R + wid * 16;
        const int mr0 = m0 + rsub;
        const int mr1 = mr0 + 8;

        // ---------------- PE directly into A fragments ----------------------
        uint32_t aF[8][4];
        float s0[2], s1[2], s2[2];
        {
            const float* rm = rotmat + b * 9;
            float r00 = rm[0], r01 = rm[1], r02 = rm[2];
            float r10 = rm[3], r11 = rm[4], r12 = rm[5];
            float r20 = rm[6], r21 = rm[7], r22 = rm[8];
            #pragma unroll
            for (int rr = 0; rr < 2; ++rr) {
                int m  = rr == 0 ? mr0 : mr1;
                int mc = (m < M) ? m : (M - 1);
                int idx = midx[mc];
                float c0 = pc[idx * 3 + 0];
                float c1 = pc[idx * 3 + 1];
                float c2 = pc[idx * 3 + 2];
                s0[rr] = c0 * r00 + c1 * r10 + c2 * r20;
                s1[rr] = c0 * r01 + c1 * r11 + c2 * r21;
                s2[rr] = c0 * r02 + c1 * r12 + c2 * r22;
            }
        }
        #pragma unroll
        for (int j = 0; j < 8; ++j) {
            int p0 = 8 * j + 2 * q;
            float g00 = bg[p0],     g01 = bg[64 + p0],     g02 = bg[128 + p0];
            float g10 = bg[p0 + 1], g11 = bg[64 + p0 + 1], g12 = bg[128 + p0 + 1];
            int slotL = (j & 1) * 2;      // k-low slots for even j, k-high for odd
            #pragma unroll
            for (int rr = 0; rr < 2; ++rr) {
                float d0 = s0[rr] * g00 + s1[rr] * g01 + s2[rr] * g02;
                float d1 = s0[rr] * g10 + s1[rr] * g11 + s2[rr] * g12;
                // proj = 2*pi*d  =>  reduced arg = 2*pi*(d - round(d))
                float x0 = TWOPI * (d0 - rintf(d0));
                float x1 = TWOPI * (d1 - rintf(d1));
                float sv0, cv0, sv1, cv1;
                fast_sincos(x0, &sv0, &cv0);     // MUFU fast path, arg in [-pi,pi]
                fast_sincos(x1, &sv1, &cv1);
                aF[j >> 1][slotL + rr]       = packh2(sv0, sv1);   // sin: k 0..63
                aF[(j >> 1) + 4][slotL + rr] = packh2(cv0, cv1);   // cos: k 64..127
            }
        }

        float acc[16][4];
        const uint32_t wOff = nLoc * 256;

        // layer 0 (acc pre-seeded with zb row for image b)
        layer_mma(aF, acc, sbase + OFF_W0 + wOff, bSelKg, nl7, sZB + b * HID, q);
        epi_pack(aF, acc);
        // layer 1
        layer_mma(aF, acc, sbase + OFF_W1 + wOff, bSelKg, nl7, sB1, q);
        epi_pack(aF, acc);
        // layer 2
        layer_mma(aF, acc, sbase + OFF_W2 + wOff, bSelKg, nl7, sB2, q);
        // h = relu(acc) as fp16 A fragments (bias b2 already in acc)
        epi_pack(aF, acc);

        // -------- output layer as one MMA pass: D = h @ wout^T (n=8) -------
        {
            float acc2[4] = {bo0, bo1, bo0, bo1};   // bout pre-seeded
            const uint32_t woBase = sbase + OFF_WO16 + wOff;
            #pragma unroll
            for (int kt = 0; kt < 8; ++kt) {
                uint32_t ad = woBase + ((((uint32_t)(2 * kt) + bSelKg) ^ nl7) << 4);
                uint32_t b0r, b1r, b2r, b3r;
                ldsm4(b0r, b1r, b2r, b3r, ad);   // b2r,b3r = zero rows 8-15
                mma_f16(acc2, aF[kt][0], aF[kt][1], aF[kt][2], aF[kt][3], b0r, b1r);
            }
            // thread q owns D cols 2q,2q+1 -> q==0 holds out0,out1 directly
            if (q == 0) {
                if (mr0 < M) {
                    int idx = midx[mr0];
                    *reinterpret_cast<float2*>(out + ((size_t)b * NPIX + idx) * 2) =
                        make_float2(acc2[0], acc2[1]);
                }
                if (mr1 < M) {
                    int idx = midx[mr1];
                    *reinterpret_cast<float2*>(out + ((size_t)b * NPIX + idx) * 2) =
                        make_float2(acc2[2], acc2[3]);
                }
            }
        }

        unit += gridDim.x;
    }
}

extern "C" void kernel_launch(void* const* d_in, const int* in_sizes, int n_in,
                              void* d_out, int out_size)
{
    const float* z      = (const float*)d_in[0];
    const float* rotmat = (const float*)d_in[1];
    const float* pc     = (const float*)d_in[2];
    const int*   midx   = (const int*)  d_in[3];
    const float* bg     = (const float*)d_in[4];
    const float* w0     = (const float*)d_in[5];
    const float* b0     = (const float*)d_in[6];
    const float* w1     = (const float*)d_in[7];
    const float* b1     = (const float*)d_in[8];
    const float* w2     = (const float*)d_in[9];
    const float* b2     = (const float*)d_in[10];
    const float* wout   = (const float*)d_in[11];
    const float* bout   = (const float*)d_in[12];
    float* out = (float*)d_out;

    const int M = in_sizes[3];
    const int B = in_sizes[0] / ZD;
    const int tiles = (M + TILE_R - 1) / TILE_R;
    const int total = B * tiles;

    // zero whole output (poisoned; only masked pixels are written)
    {
        int n4 = out_size / 4;
        int blocks = (n4 + 255) / 256;
        if (blocks > 2048) blocks = 2048;
        ifv_zero_kernel<<<blocks, 256>>>((float4*)out, n4);
    }

    static bool attr_done = false;
    if (!attr_done) {
        cudaFuncSetAttribute(ifv_binit_kernel,
                             cudaFuncAttributeMaxDynamicSharedMemorySize, SMEM_BYTES);
        attr_done = true;
    }
    int grid = total < GRID_P ? total : GRID_P;
    ifv_binit_kernel<<<grid, NTHREADS, SMEM_BYTES>>>(
        z, rotmat, pc, midx, bg, w0, b0, w1, b1, w2, b2, wout, bout,
        out, M, tiles, total, B);
}

// round 16
// speedup vs baseline: 1.0412x; 1.0412x over previous
#include <cuda_runtime.h>
#include <cuda_fp16.h>
#include <math.h>
#include <stdint.h>

#define ZD      8
#define HID     128
#define NPIX    65536
#define TILE_R  256          // 16 warps x 16 rows
#define NTHREADS 512
#define GRID_P  148

// ---------------- SMEM byte offsets ----------------------------------------
#define OFF_W0   0            // 128x128 half [n][k] swizzled = 32768
#define OFF_W1   32768
#define OFF_W2   65536
#define OFF_ZBH  98304        // 16 images x 64 half2 (b0 + z@w0[0:8]) = 4096
#define OFF_B1H  102400       // 64 half2 = 256
#define OFF_B2H  102656       // 64 half2 = 256
#define OFF_WO16 102912       // 16 rows x 128 half (wout^T padded) = 4096
#define SMEM_BYTES 107008

// half-index swizzle for weights: element (n,k) of [n][128]; 16B granules
#define HSW(n, k) ((n) * 128 + (((((k) >> 3) ^ ((n) & 7)) << 3) | ((k) & 7)))

__device__ __forceinline__ uint32_t smem_u32(const void* p) {
    uint32_t a;
    asm("{ .reg .u64 t; cvta.to.shared.u64 t, %1; cvt.u32.u64 %0, t; }" : "=r"(a) : "l"(p));
    return a;
}
__device__ __forceinline__ void ldsm4(uint32_t& r0, uint32_t& r1, uint32_t& r2, uint32_t& r3,
                                      uint32_t addr) {
    asm volatile("ldmatrix.sync.aligned.m8n8.x4.shared.b16 {%0,%1,%2,%3}, [%4];"
                 : "=r"(r0), "=r"(r1), "=r"(r2), "=r"(r3) : "r"(addr));
}
__device__ __forceinline__ void mma_f16(float c[4],
                                        uint32_t a0, uint32_t a1, uint32_t a2, uint32_t a3,
                                        uint32_t b0, uint32_t b1) {
    asm volatile("mma.sync.aligned.m16n8k16.row.col.f32.f16.f16.f32 "
                 "{%0,%1,%2,%3}, {%4,%5,%6,%7}, {%8,%9}, {%0,%1,%2,%3};"
                 : "+f"(c[0]), "+f"(c[1]), "+f"(c[2]), "+f"(c[3])
                 : "r"(a0), "r"(a1), "r"(a2), "r"(a3), "r"(b0), "r"(b1));
}
__device__ __forceinline__ uint32_t packh2(float a, float b) {
    __half2 h = __floats2half2_rn(a, b);
    return *reinterpret_cast<uint32_t*>(&h);
}
// pack two f32, add half2 bias, relu — all in packed half2
__device__ __forceinline__ uint32_t h2_bias_relu(float a, float b, uint32_t bias2) {
    __half2 v = __floats2half2_rn(a, b);
    __half2 bh = *reinterpret_cast<__half2*>(&bias2);
    __half2 zz = __float2half2_rn(0.f);
    v = __hmax2(__hadd2(v, bh), zz);
    return *reinterpret_cast<uint32_t*>(&v);
}
__device__ __forceinline__ void fast_sincos(float x, float* s, float* c) {
    *s = __sinf(x);
    *c = __cosf(x);
}

// one full layer: acc[16][4] = A(aF) @ W(128x128), per-warp 16x128 strip.
__device__ __forceinline__ void layer_mma(const uint32_t aF[8][4], float acc[16][4],
                                          uint32_t wB0, uint32_t bSelKg, uint32_t nl7) {
    #pragma unroll
    for (int nt = 0; nt < 16; ++nt)
        #pragma unroll
        for (int d = 0; d < 4; ++d) acc[nt][d] = 0.f;

    #pragma unroll
    for (int kt = 0; kt < 8; ++kt) {
        // swizzle XOR is independent of ng (n & 7 == nLoc & 7)
        uint32_t base = wB0 + ((((uint32_t)(2 * kt) + bSelKg) ^ nl7) << 4);
        #pragma unroll
        for (int hg = 0; hg < 2; ++hg) {
            uint32_t bf[8][2];
            #pragma unroll
            for (int ngl = 0; ngl < 4; ++ngl) {
                uint32_t ad = base + (uint32_t)(hg * 4 + ngl) * 4096;
                ldsm4(bf[2 * ngl][0], bf[2 * ngl][1],
                      bf[2 * ngl + 1][0], bf[2 * ngl + 1][1], ad);
            }
            #pragma unroll
            for (int ntl = 0; ntl < 8; ++ntl)
                mma_f16(acc[hg * 8 + ntl], aF[kt][0], aF[kt][1], aF[kt][2], aF[kt][3],
                        bf[ntl][0], bf[ntl][1]);
        }
    }
}

// packed-half2 epilogue: bias + relu + pack -> next layer's A fragments
__device__ __forceinline__ void epi_pack(uint32_t aF[8][4], const float acc[16][4],
                                         const uint32_t* __restrict__ biasH2, int q) {
    #pragma unroll
    for (int kt = 0; kt < 8; ++kt) {
        uint32_t bA = biasH2[8 * kt + q];
        uint32_t bB = biasH2[8 * kt + q + 4];
        aF[kt][0] = h2_bias_relu(acc[2 * kt][0],     acc[2 * kt][1],     bA);
        aF[kt][1] = h2_bias_relu(acc[2 * kt][2],     acc[2 * kt][3],     bA);
        aF[kt][2] = h2_bias_relu(acc[2 * kt + 1][0], acc[2 * kt + 1][1], bB);
        aF[kt][3] = h2_bias_relu(acc[2 * kt + 1][2], acc[2 * kt + 1][3], bB);
    }
}

__global__ void ifv_zero_kernel(float4* __restrict__ out, int n4) {
    int i = blockIdx.x * blockDim.x + threadIdx.x;
    int stride = gridDim.x * blockDim.x;
    float4 zv = make_float4(0.f, 0.f, 0.f, 0.f);
    for (; i < n4; i += stride) out[i] = zv;
}

__global__ __launch_bounds__(NTHREADS)
void ifv_cc_kernel(const float* __restrict__ z,
                   const float* __restrict__ rotmat,
                   const float* __restrict__ pc,
                   const int*   __restrict__ midx,
                   const float* __restrict__ bg,
                   const float* __restrict__ w0, const float* __restrict__ b0,
                   const float* __restrict__ w1, const float* __restrict__ b1,
                   const float* __restrict__ w2, const float* __restrict__ b2,
                   const float* __restrict__ wout, const float* __restrict__ bout,
                   float* __restrict__ out, int M, int tiles, int total, int nimg)
{
    extern __shared__ char smem[];
    __half*    sW0  = (__half*)(smem + OFF_W0);
    __half*    sW1  = (__half*)(smem + OFF_W1);
    __half*    sW2  = (__half*)(smem + OFF_W2);
    uint32_t*  sZBh = (uint32_t*)(smem + OFF_ZBH);   // per image: 64 half2
    uint32_t*  sB1h = (uint32_t*)(smem + OFF_B1H);   // 64 half2
    uint32_t*  sB2h = (uint32_t*)(smem + OFF_B2H);   // 64 half2
    __half*    sWo  = (__half*)(smem + OFF_WO16);    // 16x128, rows 2..15 zero

    const uint32_t sbase = smem_u32(smem);
    const int t    = threadIdx.x;
    const int wid  = t >> 5;
    const int lane = t & 31;
    const int q    = lane & 3;
    const int rsub = lane >> 2;                  // 0..7

    // ---------------- one-time staging (weights fp16 [n][k] swizzled) ------
    for (int i = t; i < HID * HID; i += NTHREADS) {
        int k = i >> 7, n = i & 127;
        int sw = HSW(n, k);
        sW0[sw] = __float2half(w0[(k + ZD) * HID + n]);  // z rows folded into zb
        sW1[sw] = __float2half(w1[k * HID + n]);
        sW2[sw] = __float2half(w2[k * HID + n]);
    }
    // wout^T panel: row n (0..15), col k; rows 0,1 = wout[:,0], wout[:,1]
    for (int i = t; i < 16 * HID; i += NTHREADS) {
        int n = i >> 7, k = i & 127;
        float v = (n < 2) ? wout[k * 2 + n] : 0.f;
        sWo[HSW(n, k)] = __float2half(v);
    }
    // zbh[b][c/2] = half2( b0 + z@w0[0:8] )
    for (int i = t; i < nimg * 64; i += NTHREADS) {
        int bb = i >> 6, c = (i & 63) * 2;
        float a0 = b0[c], a1 = b0[c + 1];
        #pragma unroll
        for (int k = 0; k < ZD; ++k) {
            float zv = z[bb * ZD + k];
            a0 = fmaf(zv, w0[k * HID + c],     a0);
            a1 = fmaf(zv, w0[k * HID + c + 1], a1);
        }
        sZBh[i] = packh2(a0, a1);
    }
    if (t < 64) {
        sB1h[t] = packh2(b1[2 * t], b1[2 * t + 1]);
        sB2h[t] = packh2(b2[2 * t], b2[2 * t + 1]);
    }
    __syncthreads();   // the ONLY block barrier

    const uint32_t bSelKg = (uint32_t)((lane >> 3) & 1);
    const uint32_t nLoc   = (uint32_t)(((lane >> 4) << 3) + (lane & 7));
    const uint32_t nl7    = nLoc & 7;
    const float bo0 = bout[0], bo1 = bout[1];
    const float TWOPI = 6.28318530717958647692f;
    // plane coords are affine in pixel index; z-component is 0.
    const float CSTEP = 2.0f / 255.0f;
    const float COFF  = -1.0f - 1.0f / 128.0f;
    const float2* bg2 = reinterpret_cast<const float2*>(bg);

    int unit = blockIdx.x;
    while (unit < total) {
        const int b  = unit / tiles;
        const int m0 = (unit - b * tiles) * TILE_R + wid * 16;
        const int mr0 = m0 + rsub;
        const int mr1 = mr0 + 8;

        // ---------------- PE directly into A fragments ----------------------
        uint32_t aF[8][4];
        float s0[2], s1[2], s2[2];
        {
            const float* rm = rotmat + b * 9;
            float r00 = rm[0], r01 = rm[1], r02 = rm[2];
            float r10 = rm[3], r11 = rm[4], r12 = rm[5];
            #pragma unroll
            for (int rr = 0; rr < 2; ++rr) {
                int m  = rr == 0 ? mr0 : mr1;
                int mc = (m < M) ? m : (M - 1);
                int idx = midx[mc];
                // coords: c0 = lin[idx&255] - 1/128, c1 = lin[idx>>8] - 1/128, c2 = 0
                float c0 = fmaf((float)(idx & 255), CSTEP, COFF);
                float c1 = fmaf((float)(idx >> 8),  CSTEP, COFF);
                s0[rr] = c0 * r00 + c1 * r10;
                s1[rr] = c0 * r01 + c1 * r11;
                s2[rr] = c0 * r02 + c1 * r12;
            }
        }
        #pragma unroll
        for (int j = 0; j < 8; ++j) {
            int p0 = 8 * j + 2 * q;                    // even
            float2 gA = bg2[p0 >> 1];                  // bg[p0], bg[p0+1]
            float2 gB = bg2[(64 + p0) >> 1];
            float2 gC = bg2[(128 + p0) >> 1];
            int slotL = (j & 1) * 2;      // k-low slots for even j, k-high for odd
            #pragma unroll
            for (int rr = 0; rr < 2; ++rr) {
                float d0 = s0[rr] * gA.x + s1[rr] * gB.x + s2[rr] * gC.x;
                float d1 = s0[rr] * gA.y + s1[rr] * gB.y + s2[rr] * gC.y;
                // proj = 2*pi*d  =>  reduced arg = 2*pi*(d - round(d))
                float x0 = TWOPI * (d0 - rintf(d0));
                float x1 = TWOPI * (d1 - rintf(d1));
                float sv0, cv0, sv1, cv1;
                fast_sincos(x0, &sv0, &cv0);     // MUFU fast path, arg in [-pi,pi]
                fast_sincos(x1, &sv1, &cv1);
                aF[j >> 1][slotL + rr]       = packh2(sv0, sv1);   // sin: k 0..63
                aF[(j >> 1) + 4][slotL + rr] = packh2(cv0, cv1);   // cos: k 64..127
            }
        }

        float acc[16][4];
        const uint32_t wOff = nLoc * 256;

        // layer 0 (bias = zb half2 row for image b)
        layer_mma(aF, acc, sbase + OFF_W0 + wOff, bSelKg, nl7);
        epi_pack(aF, acc, sZBh + b * 64, q);
        // layer 1
        layer_mma(aF, acc, sbase + OFF_W1 + wOff, bSelKg, nl7);
        epi_pack(aF, acc, sB1h, q);
        // layer 2
        layer_mma(aF, acc, sbase + OFF_W2 + wOff, bSelKg, nl7);
        // h = relu(acc + b2) as fp16 A fragments
        epi_pack(aF, acc, sB2h, q);

        // -------- output layer as one MMA pass: D = h @ wout^T (n=8) -------
        {
            float acc2[4] = {0.f, 0.f, 0.f, 0.f};
            const uint32_t woBase = sbase + OFF_WO16 + wOff;
            #pragma unroll
            for (int kt = 0; kt < 8; ++kt) {
                uint32_t ad = woBase + ((((uint32_t)(2 * kt) + bSelKg) ^ nl7) << 4);
                uint32_t b0r, b1r, b2r, b3r;
                ldsm4(b0r, b1r, b2r, b3r, ad);   // b2r,b3r = zero rows 8-15
                mma_f16(acc2, aF[kt][0], aF[kt][1], aF[kt][2], aF[kt][3], b0r, b1r);
            }
            // thread q owns D cols 2q,2q+1 -> q==0 holds out0,out1 directly
            if (q == 0) {
                if (mr0 < M) {
                    int idx = midx[mr0];
                    *reinterpret_cast<float2*>(out + ((size_t)b * NPIX + idx) * 2) =
                        make_float2(acc2[0] + bo0, acc2[1] + bo1);
                }
                if (mr1 < M) {
                    int idx = midx[mr1];
                    *reinterpret_cast<float2*>(out + ((size_t)b * NPIX + idx) * 2) =
                        make_float2(acc2[2] + bo0, acc2[3] + bo1);
                }
            }
        }

        unit += gridDim.x;
    }
}

extern "C" void kernel_launch(void* const* d_in, const int* in_sizes, int n_in,
                              void* d_out, int out_size)
{
    const float* z      = (const float*)d_in[0];
    const float* rotmat = (const float*)d_in[1];
    const float* pc     = (const float*)d_in[2];
    const int*   midx   = (const int*)  d_in[3];
    const float* bg     = (const float*)d_in[4];
    const float* w0     = (const float*)d_in[5];
    const float* b0     = (const float*)d_in[6];
    const float* w1     = (const float*)d_in[7];
    const float* b1     = (const float*)d_in[8];
    const float* w2     = (const float*)d_in[9];
    const float* b2     = (const float*)d_in[10];
    const float* wout   = (const float*)d_in[11];
    const float* bout   = (const float*)d_in[12];
    float* out = (float*)d_out;

    const int M = in_sizes[3];
    const int B = in_sizes[0] / ZD;
    const int tiles = (M + TILE_R - 1) / TILE_R;
    const int total = B * tiles;

    // zero whole output (poisoned; only masked pixels are written)
    {
        int n4 = out_size / 4;
        int blocks = (n4 + 255) / 256;
        if (blocks > 2048) blocks = 2048;
        ifv_zero_kernel<<<blocks, 256>>>((float4*)out, n4);
    }

    static bool attr_done = false;
    if (!attr_done) {
        cudaFuncSetAttribute(ifv_cc_kernel,
                             cudaFuncAttributeMaxDynamicSharedMemorySize, SMEM_BYTES);
        attr_done = true;
    }
    int grid = total < GRID_P ? total : GRID_P;
    ifv_cc_kernel<<<grid, NTHREADS, SMEM_BYTES>>>(
        z, rotmat, pc, midx, bg, w0, b0, w1, b1, w2, b2, wout, bout,
        out, M, tiles, total, B);
}

// round 17
// speedup vs baseline: 1.0445x; 1.0032x over previous
#include <cuda_runtime.h>
#include <cuda_fp16.h>
#include <math.h>
#include <stdint.h>

#define ZD      8
#define HID     128
#define NPIX    65536
#define TILE_R  256          // 16 warps x 16 rows
#define NTHREADS 512
#define GRID_P  148

// ---------------- SMEM byte offsets ----------------------------------------
#define OFF_W0   0            // 128x128 half [n][k] swizzled = 32768
#define OFF_W1   32768
#define OFF_W2   65536
#define OFF_ZBH  98304        // 16 images x 64 half2 (b0 + z@w0[0:8]) = 4096
#define OFF_B1H  102400       // 64 half2 = 256
#define OFF_B2H  102656       // 64 half2 = 256
#define OFF_WO8  102912       // 8 rows x 128 half (wout^T padded) = 2048
#define SMEM_BYTES 104960

// half-index swizzle for weights: element (n,k) of [n][128]; 16B granules
#define HSW(n, k) ((n) * 128 + (((((k) >> 3) ^ ((n) & 7)) << 3) | ((k) & 7)))

__device__ __forceinline__ uint32_t smem_u32(const void* p) {
    uint32_t a;
    asm("{ .reg .u64 t; cvta.to.shared.u64 t, %1; cvt.u32.u64 %0, t; }" : "=r"(a) : "l"(p));
    return a;
}
__device__ __forceinline__ void ldsm4(uint32_t& r0, uint32_t& r1, uint32_t& r2, uint32_t& r3,
                                      uint32_t addr) {
    asm volatile("ldmatrix.sync.aligned.m8n8.x4.shared.b16 {%0,%1,%2,%3}, [%4];"
                 : "=r"(r0), "=r"(r1), "=r"(r2), "=r"(r3) : "r"(addr));
}
__device__ __forceinline__ void ldsm2(uint32_t& r0, uint32_t& r1, uint32_t addr) {
    asm volatile("ldmatrix.sync.aligned.m8n8.x2.shared.b16 {%0,%1}, [%2];"
                 : "=r"(r0), "=r"(r1) : "r"(addr));
}
__device__ __forceinline__ void mma_f16(float c[4],
                                        uint32_t a0, uint32_t a1, uint32_t a2, uint32_t a3,
                                        uint32_t b0, uint32_t b1) {
    asm volatile("mma.sync.aligned.m16n8k16.row.col.f32.f16.f16.f32 "
                 "{%0,%1,%2,%3}, {%4,%5,%6,%7}, {%8,%9}, {%0,%1,%2,%3};"
                 : "+f"(c[0]), "+f"(c[1]), "+f"(c[2]), "+f"(c[3])
                 : "r"(a0), "r"(a1), "r"(a2), "r"(a3), "r"(b0), "r"(b1));
}
__device__ __forceinline__ uint32_t packh2(float a, float b) {
    __half2 h = __floats2half2_rn(a, b);
    return *reinterpret_cast<uint32_t*>(&h);
}
// pack two f32, add half2 bias, relu — all in packed half2
__device__ __forceinline__ uint32_t h2_bias_relu(float a, float b, uint32_t bias2) {
    __half2 v = __floats2half2_rn(a, b);
    __half2 bh = *reinterpret_cast<__half2*>(&bias2);
    __half2 zz = __float2half2_rn(0.f);
    v = __hmax2(__hadd2(v, bh), zz);
    return *reinterpret_cast<uint32_t*>(&v);
}
__device__ __forceinline__ void fast_sincos(float x, float* s, float* c) {
    *s = __sinf(x);
    *c = __cosf(x);
}

// one full layer: acc[16][4] = A(aF) @ W(128x128), per-warp 16x128 strip.
__device__ __forceinline__ void layer_mma(const uint32_t aF[8][4], float acc[16][4],
                                          uint32_t wB0, uint32_t bSelKg, uint32_t nl7) {
    #pragma unroll
    for (int nt = 0; nt < 16; ++nt)
        #pragma unroll
        for (int d = 0; d < 4; ++d) acc[nt][d] = 0.f;

    #pragma unroll
    for (int kt = 0; kt < 8; ++kt) {
        // swizzle XOR is independent of ng (n & 7 == nLoc & 7)
        uint32_t base = wB0 + ((((uint32_t)(2 * kt) + bSelKg) ^ nl7) << 4);
        #pragma unroll
        for (int hg = 0; hg < 2; ++hg) {
            uint32_t bf[8][2];
            #pragma unroll
            for (int ngl = 0; ngl < 4; ++ngl) {
                uint32_t ad = base + (uint32_t)(hg * 4 + ngl) * 4096;
                ldsm4(bf[2 * ngl][0], bf[2 * ngl][1],
                      bf[2 * ngl + 1][0], bf[2 * ngl + 1][1], ad);
            }
            #pragma unroll
            for (int ntl = 0; ntl < 8; ++ntl)
                mma_f16(acc[hg * 8 + ntl], aF[kt][0], aF[kt][1], aF[kt][2], aF[kt][3],
                        bf[ntl][0], bf[ntl][1]);
        }
    }
}

// packed-half2 epilogue: bias + relu + pack -> next layer's A fragments
__device__ __forceinline__ void epi_pack(uint32_t aF[8][4], const float acc[16][4],
                                         const uint32_t* __restrict__ biasH2, int q) {
    #pragma unroll
    for (int kt = 0; kt < 8; ++kt) {
        uint32_t bA = biasH2[8 * kt + q];
        uint32_t bB = biasH2[8 * kt + q + 4];
        aF[kt][0] = h2_bias_relu(acc[2 * kt][0],     acc[2 * kt][1],     bA);
        aF[kt][1] = h2_bias_relu(acc[2 * kt][2],     acc[2 * kt][3],     bA);
        aF[kt][2] = h2_bias_relu(acc[2 * kt + 1][0], acc[2 * kt + 1][1], bB);
        aF[kt][3] = h2_bias_relu(acc[2 * kt + 1][2], acc[2 * kt + 1][3], bB);
    }
}

__global__ void ifv_zero_kernel(float4* __restrict__ out, int n4) {
    int i = blockIdx.x * blockDim.x + threadIdx.x;
    int stride = gridDim.x * blockDim.x;
    float4 zv = make_float4(0.f, 0.f, 0.f, 0.f);
    for (; i < n4; i += stride) out[i] = zv;
}

__global__ __launch_bounds__(NTHREADS)
void ifv_f_kernel(const float* __restrict__ z,
                  const float* __restrict__ rotmat,
                  const float* __restrict__ pc,
                  const int*   __restrict__ midx,
                  const float* __restrict__ bg,
                  const float* __restrict__ w0, const float* __restrict__ b0,
                  const float* __restrict__ w1, const float* __restrict__ b1,
                  const float* __restrict__ w2, const float* __restrict__ b2,
                  const float* __restrict__ wout, const float* __restrict__ bout,
                  float* __restrict__ out, int M, int tiles, int total, int nimg)
{
    extern __shared__ char smem[];
    __half*    sW0  = (__half*)(smem + OFF_W0);
    __half*    sW1  = (__half*)(smem + OFF_W1);
    __half*    sW2  = (__half*)(smem + OFF_W2);
    uint32_t*  sZBh = (uint32_t*)(smem + OFF_ZBH);   // per image: 64 half2
    uint32_t*  sB1h = (uint32_t*)(smem + OFF_B1H);   // 64 half2
    uint32_t*  sB2h = (uint32_t*)(smem + OFF_B2H);   // 64 half2
    __half*    sWo  = (__half*)(smem + OFF_WO8);     // 8x128, rows 2..7 zero

    const uint32_t sbase = smem_u32(smem);
    const int t    = threadIdx.x;
    const int wid  = t >> 5;
    const int lane = t & 31;
    const int q    = lane & 3;
    const int rsub = lane >> 2;                  // 0..7

    // ---------------- one-time staging (weights fp16 [n][k] swizzled) ------
    for (int i = t; i < HID * HID; i += NTHREADS) {
        int k = i >> 7, n = i & 127;
        int sw = HSW(n, k);
        sW0[sw] = __float2half(w0[(k + ZD) * HID + n]);  // z rows folded into zb
        sW1[sw] = __float2half(w1[k * HID + n]);
        sW2[sw] = __float2half(w2[k * HID + n]);
    }
    // wout^T panel: row n (0..7), col k; rows 0,1 = wout[:,0], wout[:,1]
    for (int i = t; i < 8 * HID; i += NTHREADS) {
        int n = i >> 7, k = i & 127;
        float v = (n < 2) ? wout[k * 2 + n] : 0.f;
        sWo[HSW(n, k)] = __float2half(v);
    }
    // zbh[b][c/2] = half2( b0 + z@w0[0:8] )
    for (int i = t; i < nimg * 64; i += NTHREADS) {
        int bb = i >> 6, c = (i & 63) * 2;
        float a0 = b0[c], a1 = b0[c + 1];
        #pragma unroll
        for (int k = 0; k < ZD; ++k) {
            float zv = z[bb * ZD + k];
            a0 = fmaf(zv, w0[k * HID + c],     a0);
            a1 = fmaf(zv, w0[k * HID + c + 1], a1);
        }
        sZBh[i] = packh2(a0, a1);
    }
    if (t < 64) {
        sB1h[t] = packh2(b1[2 * t], b1[2 * t + 1]);
        sB2h[t] = packh2(b2[2 * t], b2[2 * t + 1]);
    }
    __syncthreads();   // the ONLY block barrier

    const uint32_t bSelKg = (uint32_t)((lane >> 3) & 1);
    const uint32_t nLoc   = (uint32_t)(((lane >> 4) << 3) + (lane & 7));
    const uint32_t nl7    = nLoc & 7;
    // ldsm2 uses lanes 0-15 addresses: n row = lane&7, k-granule parity = (lane>>3)&1
    const uint32_t oRow   = (uint32_t)(lane & 7);
    const float bo0 = bout[0], bo1 = bout[1];
    const float TWOPI = 6.28318530717958647692f;
    // plane coords are affine in pixel index; z-component is 0.
    const float CSTEP = 2.0f / 255.0f;
    const float COFF  = -1.0f - 1.0f / 128.0f;
    const float2* bg2 = reinterpret_cast<const float2*>(bg);

    int unit = blockIdx.x;
    while (unit < total) {
        const int b  = unit / tiles;
        const int m0 = (unit - b * tiles) * TILE_R + wid * 16;
        const int mr0 = m0 + rsub;
        const int mr1 = mr0 + 8;

        // ---------------- PE directly into A fragments ----------------------
        uint32_t aF[8][4];
        float s0[2], s1[2], s2[2];
        {
            const float* rm = rotmat + b * 9;
            float r00 = rm[0], r01 = rm[1], r02 = rm[2];
            float r10 = rm[3], r11 = rm[4], r12 = rm[5];
            #pragma unroll
            for (int rr = 0; rr < 2; ++rr) {
                int m  = rr == 0 ? mr0 : mr1;
                int mc = (m < M) ? m : (M - 1);
                int idx = midx[mc];
                // coords: c0 = lin[idx&255] - 1/128, c1 = lin[idx>>8] - 1/128, c2 = 0
                float c0 = fmaf((float)(idx & 255), CSTEP, COFF);
                float c1 = fmaf((float)(idx >> 8),  CSTEP, COFF);
                s0[rr] = c0 * r00 + c1 * r10;
                s1[rr] = c0 * r01 + c1 * r11;
                s2[rr] = c0 * r02 + c1 * r12;
            }
        }
        #pragma unroll
        for (int j = 0; j < 8; ++j) {
            int p0 = 8 * j + 2 * q;                    // even
            float2 gA = bg2[p0 >> 1];                  // bg[p0], bg[p0+1]
            float2 gB = bg2[(64 + p0) >> 1];
            float2 gC = bg2[(128 + p0) >> 1];
            int slotL = (j & 1) * 2;      // k-low slots for even j, k-high for odd
            #pragma unroll
            for (int rr = 0; rr < 2; ++rr) {
                float d0 = s0[rr] * gA.x + s1[rr] * gB.x + s2[rr] * gC.x;
                float d1 = s0[rr] * gA.y + s1[rr] * gB.y + s2[rr] * gC.y;
                // proj = 2*pi*d  =>  reduced arg = 2*pi*(d - round(d))
                float x0 = TWOPI * (d0 - rintf(d0));
                float x1 = TWOPI * (d1 - rintf(d1));
                float sv0, cv0, sv1, cv1;
                fast_sincos(x0, &sv0, &cv0);     // MUFU fast path, arg in [-pi,pi]
                fast_sincos(x1, &sv1, &cv1);
                aF[j >> 1][slotL + rr]       = packh2(sv0, sv1);   // sin: k 0..63
                aF[(j >> 1) + 4][slotL + rr] = packh2(cv0, cv1);   // cos: k 64..127
            }
        }

        float acc[16][4];
        const uint32_t wOff = nLoc * 256;

        // layer 0 (bias = zb half2 row for image b)
        layer_mma(aF, acc, sbase + OFF_W0 + wOff, bSelKg, nl7);
        epi_pack(aF, acc, sZBh + b * 64, q);
        // layer 1
        layer_mma(aF, acc, sbase + OFF_W1 + wOff, bSelKg, nl7);
        epi_pack(aF, acc, sB1h, q);
        // layer 2
        layer_mma(aF, acc, sbase + OFF_W2 + wOff, bSelKg, nl7);
        // h = relu(acc + b2) as fp16 A fragments
        epi_pack(aF, acc, sB2h, q);

        // -------- output layer as one MMA pass: D = h @ wout^T (n=8) -------
        // ldsm x2: only n rows 0-7 (rows 0,1 carry wout; 2-7 zero)
        {
            float acc2[4] = {0.f, 0.f, 0.f, 0.f};
            const uint32_t woBase = sbase + OFF_WO8 + oRow * 256;
            #pragma unroll
            for (int kt = 0; kt < 8; ++kt) {
                uint32_t ad = woBase + ((((uint32_t)(2 * kt) + bSelKg) ^ oRow) << 4);
                uint32_t b0r, b1r;
                ldsm2(b0r, b1r, ad);
                mma_f16(acc2, aF[kt][0], aF[kt][1], aF[kt][2], aF[kt][3], b0r, b1r);
            }
            // thread q owns D cols 2q,2q+1 -> q==0 holds out0,out1 directly
            if (q == 0) {
                if (mr0 < M) {
                    int idx = midx[mr0];
                    *reinterpret_cast<float2*>(out + ((size_t)b * NPIX + idx) * 2) =
                        make_float2(acc2[0] + bo0, acc2[1] + bo1);
                }
                if (mr1 < M) {
                    int idx = midx[mr1];
                    *reinterpret_cast<float2*>(out + ((size_t)b * NPIX + idx) * 2) =
                        make_float2(acc2[2] + bo0, acc2[3] + bo1);
                }
            }
        }

        unit += gridDim.x;
    }
}

extern "C" void kernel_launch(void* const* d_in, const int* in_sizes, int n_in,
                              void* d_out, int out_size)
{
    const float* z      = (const float*)d_in[0];
    const float* rotmat = (const float*)d_in[1];
    const float* pc     = (const float*)d_in[2];
    const int*   midx   = (const int*)  d_in[3];
    const float* bg     = (const float*)d_in[4];
    const float* w0     = (const float*)d_in[5];
    const float* b0     = (const float*)d_in[6];
    const float* w1     = (const float*)d_in[7];
    const float* b1     = (const float*)d_in[8];
    const float* w2     = (const float*)d_in[9];
    const float* b2     = (const float*)d_in[10];
    const float* wout   = (const float*)d_in[11];
    const float* bout   = (const float*)d_in[12];
    float* out = (float*)d_out;

    const int M = in_sizes[3];
    const int B = in_sizes[0] / ZD;
    const int tiles = (M + TILE_R - 1) / TILE_R;
    const int total = B * tiles;

    // zero whole output (poisoned; only masked pixels are written)
    {
        int n4 = out_size / 4;
        int blocks = (n4 + 255) / 256;
        if (blocks > 2048) blocks = 2048;
        ifv_zero_kernel<<<blocks, 256>>>((float4*)out, n4);
    }

    static bool attr_done = false;
    if (!attr_done) {
        cudaFuncSetAttribute(ifv_f_kernel,
                             cudaFuncAttributeMaxDynamicSharedMemorySize, SMEM_BYTES);
        attr_done = true;
    }
    int grid = total < GRID_P ? total : GRID_P;
    ifv_f_kernel<<<grid, NTHREADS, SMEM_BYTES>>>(
        z, rotmat, pc, midx, bg, w0, b0, w1, b1, w2, b2, wout, bout,
        out, M, tiles, total, B);
}